// round 17
// baseline (speedup 1.0000x reference)
#include <cuda_runtime.h>
#include <cuda_fp16.h>
#include <math.h>

#define MAXN 50000
#define MAXE 800000
#define MAXEPN (MAXE + MAXN)

// ---------------- scratch (device globals) ----------------------------------
__device__ __align__(16) __half g_h1[MAXN * 256];  // layer1 GEMM output (fp16)
__device__ __align__(16) float g_out1[MAXN * 256]; // layer1 aggregated+elu (fp32)
__device__ __align__(16) __half g_h2[MAXN * 64];   // layer2 GEMM output (fp16)
__device__ __align__(16) float g_as1[MAXN * 4], g_ad1[MAXN * 4];
__device__ float g_as2[MAXN], g_ad2[MAXN];
__device__ int g_deg[MAXN];                        // zero at entry (BSS / self-restored)
__device__ int g_rowptr[MAXN + 1];
__device__ int g_cursor[MAXN];
__device__ int g_csrc[MAXEPN];
__device__ int g_bsum[64];

// ---------------- stream/event resources (created once, pre-checkpoint) -----
static struct GpuRes {
    cudaStream_t s2;
    cudaEvent_t evFork, evJoin;
    GpuRes() {
        cudaStreamCreateWithFlags(&s2, cudaStreamNonBlocking);
        cudaEventCreateWithFlags(&evFork, cudaEventDisableTiming);
        cudaEventCreateWithFlags(&evJoin, cudaEventDisableTiming);
    }
} g_res;

// ---------------- CSR build --------------------------------------------------
__global__ void hist_kernel(const int* __restrict__ ei, int E, int n) {
    int idx = blockIdx.x * blockDim.x + threadIdx.x;
    int EQ = E >> 2;
    if (idx < EQ) {
        int4 d4 = *reinterpret_cast<const int4*>(&ei[E + idx * 4]);
        atomicAdd(&g_deg[d4.x], 1);
        atomicAdd(&g_deg[d4.y], 1);
        atomicAdd(&g_deg[d4.z], 1);
        atomicAdd(&g_deg[d4.w], 1);
    } else if (idx < EQ + n) {
        atomicAdd(&g_deg[idx - EQ], 1);   // self-loop
    }
}

// per-1024 exclusive scan + block total; also re-zeroes g_deg for next replay
__global__ void scan_local_kernel(int n) {
    __shared__ int wsum[32];
    int lane = threadIdx.x & 31, wid = threadIdx.x >> 5;
    int i = blockIdx.x * 1024 + threadIdx.x;
    int v = (i < n) ? g_deg[i] : 0;
    if (i < n) g_deg[i] = 0;          // self-restore invariant
    int x = v;
    #pragma unroll
    for (int o = 1; o < 32; o <<= 1) {
        int y = __shfl_up_sync(0xffffffffu, x, o);
        if (lane >= o) x += y;
    }
    if (lane == 31) wsum[wid] = x;
    __syncthreads();
    if (wid == 0) {
        int w = wsum[lane];
        int xs = w;
        #pragma unroll
        for (int o = 1; o < 32; o <<= 1) {
            int y = __shfl_up_sync(0xffffffffu, xs, o);
            if (lane >= o) xs += y;
        }
        wsum[lane] = xs - w;
    }
    __syncthreads();
    int excl = wsum[wid] + x - v;
    if (i < n) g_rowptr[i] = excl;
    if (threadIdx.x == 1023) g_bsum[blockIdx.x] = excl + v;
}

// fused: redundant per-block scan of <=64 block sums + offset add + cursor init
__global__ void scan_add_kernel(int n, int total, int nb) {
    __shared__ int s[64];
    if (threadIdx.x < 64) s[threadIdx.x] = (threadIdx.x < (unsigned)nb) ? g_bsum[threadIdx.x] : 0;
    __syncthreads();
    for (int o = 1; o < 64; o <<= 1) {
        int v = 0;
        if (threadIdx.x < 64 && threadIdx.x >= (unsigned)o) v = s[threadIdx.x - o];
        __syncthreads();
        if (threadIdx.x < 64) s[threadIdx.x] += v;
        __syncthreads();
    }
    int i = blockIdx.x * blockDim.x + threadIdx.x;
    if (i < n) {
        int blk = i >> 10;
        int boff = (blk > 0) ? s[blk - 1] : 0;
        int r = g_rowptr[i] + boff;
        g_rowptr[i] = r;
        g_cursor[i] = r;
    }
    if (i == 0) g_rowptr[n] = total;
}

__global__ void scatter_kernel(const int* __restrict__ ei, int E, int n) {
    int idx = blockIdx.x * blockDim.x + threadIdx.x;
    int EQ = E >> 2;
    if (idx < EQ) {
        int4 s4 = *reinterpret_cast<const int4*>(&ei[idx * 4]);
        int4 d4 = *reinterpret_cast<const int4*>(&ei[E + idx * 4]);
        int p0 = atomicAdd(&g_cursor[d4.x], 1);
        int p1 = atomicAdd(&g_cursor[d4.y], 1);
        int p2 = atomicAdd(&g_cursor[d4.z], 1);
        int p3 = atomicAdd(&g_cursor[d4.w], 1);
        g_csrc[p0] = s4.x;
        g_csrc[p1] = s4.y;
        g_csrc[p2] = s4.z;
        g_csrc[p3] = s4.w;
    } else if (idx < EQ + n) {
        int node = idx - EQ;
        int pos = atomicAdd(&g_cursor[node], 1);
        g_csrc[pos] = node;
    }
}

// ---------------- 3xTF32 tensor-core GEMM + fused alpha epilogue ------------
__device__ __forceinline__ void split_tf32(float v, unsigned& hi, unsigned& lo) {
    unsigned h;
    asm("cvt.rna.tf32.f32 %0, %1;" : "=r"(h) : "f"(v));
    float l = v - __uint_as_float(h);
    unsigned lw;
    asm("cvt.rna.tf32.f32 %0, %1;" : "=r"(lw) : "f"(l));
    hi = h; lo = lw;
}

__device__ __forceinline__ void mma_tf32(float& c0, float& c1, float& c2, float& c3,
                                         unsigned a0, unsigned a1, unsigned a2, unsigned a3,
                                         unsigned b0, unsigned b1) {
    asm volatile(
        "mma.sync.aligned.m16n8k8.row.col.f32.tf32.tf32.f32 "
        "{%0,%1,%2,%3},{%4,%5,%6,%7},{%8,%9},{%0,%1,%2,%3};"
        : "+f"(c0), "+f"(c1), "+f"(c2), "+f"(c3)
        : "r"(a0), "r"(a1), "r"(a2), "r"(a3), "r"(b0), "r"(b1));
}

// BM=128, BN in {128, 64}, BK=16. 256 threads = 8 warps (4 m x 2 n).
template <int BN, bool REDUCE>
__global__ void gemm_tc_kernel(const float* __restrict__ A, const float* __restrict__ B,
                               __half* __restrict__ C, int n, int k, int m,
                               const float* __restrict__ attS, const float* __restrict__ attD,
                               float* __restrict__ asOut, float* __restrict__ adOut) {
    constexpr int BM = 128, BK = 16;
    constexpr int WN = BN / 2;
    constexpr int NFRAG = WN / 8;
    constexpr int AP = BM + 8;
    constexpr int BP = BN + 8;
    constexpr int AITER = BM * BK / 4 / 256;
    constexpr int BITER = BK * BN / 4 / 256;

    __shared__ unsigned Ahi[BK][AP], Alo[BK][AP];
    __shared__ unsigned Bhi[BK][BP], Blo[BK][BP];

    int tid = threadIdx.x;
    int warp = tid >> 5, lane = tid & 31;
    int wm = warp & 3, wn = warp >> 2;
    int g = lane >> 2, t4 = lane & 3;
    int row0 = blockIdx.y * BM, col0 = blockIdx.x * BN;

    float4 aR[AITER], bR[BITER];

    auto loadTile = [&](int kt) {
        #pragma unroll
        for (int i = 0; i < AITER; i++) {
            int slot = tid + i * 256;
            int r = slot / (BK / 4), q = slot % (BK / 4);
            int gr = row0 + r;
            aR[i] = (gr < n)
                ? *reinterpret_cast<const float4*>(&A[(size_t)gr * k + kt + q * 4])
                : make_float4(0.f, 0.f, 0.f, 0.f);
        }
        #pragma unroll
        for (int i = 0; i < BITER; i++) {
            int slot = tid + i * 256;
            int kr = slot / (BN / 4), nc = slot % (BN / 4);
            bR[i] = *reinterpret_cast<const float4*>(&B[(size_t)(kt + kr) * m + col0 + nc * 4]);
        }
    };
    auto storeTile = [&]() {
        #pragma unroll
        for (int i = 0; i < AITER; i++) {
            int slot = tid + i * 256;
            int r = slot / (BK / 4), q = slot % (BK / 4);
            float v[4] = {aR[i].x, aR[i].y, aR[i].z, aR[i].w};
            #pragma unroll
            for (int j = 0; j < 4; j++) {
                unsigned h, l;
                split_tf32(v[j], h, l);
                Ahi[q * 4 + j][r] = h;
                Alo[q * 4 + j][r] = l;
            }
        }
        #pragma unroll
        for (int i = 0; i < BITER; i++) {
            int slot = tid + i * 256;
            int kr = slot / (BN / 4), nc = slot % (BN / 4);
            float v[4] = {bR[i].x, bR[i].y, bR[i].z, bR[i].w};
            #pragma unroll
            for (int j = 0; j < 4; j++) {
                unsigned h, l;
                split_tf32(v[j], h, l);
                Bhi[kr][nc * 4 + j] = h;
                Blo[kr][nc * 4 + j] = l;
            }
        }
    };

    float acc[2][NFRAG][4];
    #pragma unroll
    for (int i = 0; i < 2; i++)
        #pragma unroll
        for (int j = 0; j < NFRAG; j++)
            #pragma unroll
            for (int q = 0; q < 4; q++) acc[i][j][q] = 0.f;

    int tiles = k / BK;
    loadTile(0);
    storeTile();
    __syncthreads();

    for (int t = 0; t < tiles; t++) {
        if (t + 1 < tiles) loadTile((t + 1) * BK);
        #pragma unroll
        for (int ks = 0; ks < BK / 8; ks++) {
            int k0 = ks * 8;
            unsigned ah[2][4], al[2][4];
            #pragma unroll
            for (int mf = 0; mf < 2; mf++) {
                int rb = wm * 32 + mf * 16;
                ah[mf][0] = Ahi[k0 + t4][rb + g];
                ah[mf][1] = Ahi[k0 + t4][rb + g + 8];
                ah[mf][2] = Ahi[k0 + t4 + 4][rb + g];
                ah[mf][3] = Ahi[k0 + t4 + 4][rb + g + 8];
                al[mf][0] = Alo[k0 + t4][rb + g];
                al[mf][1] = Alo[k0 + t4][rb + g + 8];
                al[mf][2] = Alo[k0 + t4 + 4][rb + g];
                al[mf][3] = Alo[k0 + t4 + 4][rb + g + 8];
            }
            unsigned bh[NFRAG][2], bl[NFRAG][2];
            #pragma unroll
            for (int nf = 0; nf < NFRAG; nf++) {
                int cb = wn * WN + nf * 8 + g;
                bh[nf][0] = Bhi[k0 + t4][cb];
                bh[nf][1] = Bhi[k0 + t4 + 4][cb];
                bl[nf][0] = Blo[k0 + t4][cb];
                bl[nf][1] = Blo[k0 + t4 + 4][cb];
            }
            #pragma unroll
            for (int mf = 0; mf < 2; mf++)
                #pragma unroll
                for (int nf = 0; nf < NFRAG; nf++) {
                    float* c = acc[mf][nf];
                    mma_tf32(c[0], c[1], c[2], c[3],
                             ah[mf][0], ah[mf][1], ah[mf][2], ah[mf][3],
                             bh[nf][0], bh[nf][1]);
                    mma_tf32(c[0], c[1], c[2], c[3],
                             ah[mf][0], ah[mf][1], ah[mf][2], ah[mf][3],
                             bl[nf][0], bl[nf][1]);
                    mma_tf32(c[0], c[1], c[2], c[3],
                             al[mf][0], al[mf][1], al[mf][2], al[mf][3],
                             bh[nf][0], bh[nf][1]);
                }
        }
        __syncthreads();
        if (t + 1 < tiles) {
            storeTile();
            __syncthreads();
        }
    }

    // ---- write C tile (fp16) ----
    __half2* C2 = reinterpret_cast<__half2*>(C);
    #pragma unroll
    for (int mf = 0; mf < 2; mf++) {
        int rbase = row0 + wm * 32 + mf * 16;
        #pragma unroll
        for (int nf = 0; nf < NFRAG; nf++) {
            int cb = col0 + wn * WN + nf * 8 + t4 * 2;
            int r0r = rbase + g, r1r = rbase + g + 8;
            if (r0r < n)
                C2[((size_t)r0r * m + cb) >> 1] =
                    __floats2half2_rn(acc[mf][nf][0], acc[mf][nf][1]);
            if (r1r < n)
                C2[((size_t)r1r * m + cb) >> 1] =
                    __floats2half2_rn(acc[mf][nf][2], acc[mf][nf][3]);
        }
    }

    // ---- fused alpha epilogue ----
    {
        float aSv[NFRAG][2], aDv[NFRAG][2];
        int hsel = REDUCE ? 0 : ((col0 + wn * WN) >> 6);
        #pragma unroll
        for (int nf = 0; nf < NFRAG; nf++) {
            int idx = (REDUCE ? wn * WN : 0) + nf * 8 + t4 * 2;
            const float* aS = attS + hsel * 64;
            const float* aD = attD + hsel * 64;
            aSv[nf][0] = aS[idx];     aSv[nf][1] = aS[idx + 1];
            aDv[nf][0] = aD[idx];     aDv[nf][1] = aD[idx + 1];
        }
        if constexpr (REDUCE) {
            __shared__ float sDS[2][BM], sDD[2][BM];
            #pragma unroll
            for (int mf = 0; mf < 2; mf++) {
                float ds0 = 0.f, dd0 = 0.f, ds1 = 0.f, dd1 = 0.f;
                #pragma unroll
                for (int nf = 0; nf < NFRAG; nf++) {
                    ds0 += acc[mf][nf][0] * aSv[nf][0] + acc[mf][nf][1] * aSv[nf][1];
                    dd0 += acc[mf][nf][0] * aDv[nf][0] + acc[mf][nf][1] * aDv[nf][1];
                    ds1 += acc[mf][nf][2] * aSv[nf][0] + acc[mf][nf][3] * aSv[nf][1];
                    dd1 += acc[mf][nf][2] * aDv[nf][0] + acc[mf][nf][3] * aDv[nf][1];
                }
                #pragma unroll
                for (int o = 1; o <= 2; o <<= 1) {
                    ds0 += __shfl_xor_sync(0xffffffffu, ds0, o);
                    dd0 += __shfl_xor_sync(0xffffffffu, dd0, o);
                    ds1 += __shfl_xor_sync(0xffffffffu, ds1, o);
                    dd1 += __shfl_xor_sync(0xffffffffu, dd1, o);
                }
                if (t4 == 0) {
                    int rl = wm * 32 + mf * 16 + g;
                    sDS[wn][rl] = ds0;     sDD[wn][rl] = dd0;
                    sDS[wn][rl + 8] = ds1; sDD[wn][rl + 8] = dd1;
                }
            }
            __syncthreads();
            if (tid < BM) {
                int gr = row0 + tid;
                if (gr < n) {
                    asOut[gr] = sDS[0][tid] + sDS[1][tid];
                    adOut[gr] = sDD[0][tid] + sDD[1][tid];
                }
            }
        } else {
            #pragma unroll
            for (int mf = 0; mf < 2; mf++) {
                float ds0 = 0.f, dd0 = 0.f, ds1 = 0.f, dd1 = 0.f;
                #pragma unroll
                for (int nf = 0; nf < NFRAG; nf++) {
                    ds0 += acc[mf][nf][0] * aSv[nf][0] + acc[mf][nf][1] * aSv[nf][1];
                    dd0 += acc[mf][nf][0] * aDv[nf][0] + acc[mf][nf][1] * aDv[nf][1];
                    ds1 += acc[mf][nf][2] * aSv[nf][0] + acc[mf][nf][3] * aSv[nf][1];
                    dd1 += acc[mf][nf][2] * aDv[nf][0] + acc[mf][nf][3] * aDv[nf][1];
                }
                #pragma unroll
                for (int o = 1; o <= 2; o <<= 1) {
                    ds0 += __shfl_xor_sync(0xffffffffu, ds0, o);
                    dd0 += __shfl_xor_sync(0xffffffffu, dd0, o);
                    ds1 += __shfl_xor_sync(0xffffffffu, ds1, o);
                    dd1 += __shfl_xor_sync(0xffffffffu, dd1, o);
                }
                if (t4 == 0) {
                    int rbase = row0 + wm * 32 + mf * 16;
                    int r0r = rbase + g, r1r = rbase + g + 8;
                    if (r0r < n) { asOut[r0r * 4 + hsel] = ds0; adOut[r0r * 4 + hsel] = dd0; }
                    if (r1r < n) { asOut[r1r * 4 + hsel] = ds1; adOut[r1r * 4 + hsel] = dd1; }
                }
            }
        }
    }
}

// ---------------- fused softmax + aggregation, layer 1 ----------------------
// TWO warps per node, each covering all 256 channels over half the edge list;
// partials combined via smem. 4 nodes per 256-thread block.
__global__ void agg1_kernel(const float* __restrict__ as1, const float* __restrict__ ad1,
                            const __half* __restrict__ hm, const float* __restrict__ bias,
                            float* __restrict__ out, int n) {
    __shared__ float sAcc[4][256];
    __shared__ float sDen[4][32];
    int tid = threadIdx.x;
    int warp = tid >> 5, lane = tid & 31;
    int sub = warp >> 1;           // node slot 0..3
    int half = warp & 1;           // which half of the edge list
    int node = blockIdx.x * 4 + sub;
    bool active = (node < n);
    int r0 = 0, r1 = 0;
    float adv = 0.f;
    int h = lane >> 3;
    if (active) {
        int a = g_rowptr[node], b = g_rowptr[node + 1];
        int mid = a + ((b - a) >> 1);
        r0 = half ? mid : a;
        r1 = half ? b : mid;
        adv = ad1[node * 4 + h];
    }
    const uint4* hm4 = reinterpret_cast<const uint4*>(hm);
    float acc[8] = {};
    float dsum = 0.f;
    int j = r0;
    for (; j + 4 <= r1; j += 4) {
        int s0 = __ldg(&g_csrc[j]);
        int s1 = __ldg(&g_csrc[j + 1]);
        int s2 = __ldg(&g_csrc[j + 2]);
        int s3 = __ldg(&g_csrc[j + 3]);
        float e0 = __ldg(&as1[s0 * 4 + h]);
        float e1 = __ldg(&as1[s1 * 4 + h]);
        float e2 = __ldg(&as1[s2 * 4 + h]);
        float e3 = __ldg(&as1[s3 * 4 + h]);
        uint4 v0 = hm4[(size_t)s0 * 32 + lane];
        uint4 v1 = hm4[(size_t)s1 * 32 + lane];
        uint4 v2 = hm4[(size_t)s2 * 32 + lane];
        uint4 v3 = hm4[(size_t)s3 * 32 + lane];
        e0 += adv; e0 = (e0 > 0.f) ? e0 : 0.2f * e0; float w0 = __expf(e0);
        e1 += adv; e1 = (e1 > 0.f) ? e1 : 0.2f * e1; float w1 = __expf(e1);
        e2 += adv; e2 = (e2 > 0.f) ? e2 : 0.2f * e2; float w2 = __expf(e2);
        e3 += adv; e3 = (e3 > 0.f) ? e3 : 0.2f * e3; float w3 = __expf(e3);
        dsum += w0 + w1 + w2 + w3;
        {
            float2 p;
            p = __half22float2(*reinterpret_cast<__half2*>(&v0.x)); acc[0] += p.x * w0; acc[1] += p.y * w0;
            p = __half22float2(*reinterpret_cast<__half2*>(&v0.y)); acc[2] += p.x * w0; acc[3] += p.y * w0;
            p = __half22float2(*reinterpret_cast<__half2*>(&v0.z)); acc[4] += p.x * w0; acc[5] += p.y * w0;
            p = __half22float2(*reinterpret_cast<__half2*>(&v0.w)); acc[6] += p.x * w0; acc[7] += p.y * w0;
            p = __half22float2(*reinterpret_cast<__half2*>(&v1.x)); acc[0] += p.x * w1; acc[1] += p.y * w1;
            p = __half22float2(*reinterpret_cast<__half2*>(&v1.y)); acc[2] += p.x * w1; acc[3] += p.y * w1;
            p = __half22float2(*reinterpret_cast<__half2*>(&v1.z)); acc[4] += p.x * w1; acc[5] += p.y * w1;
            p = __half22float2(*reinterpret_cast<__half2*>(&v1.w)); acc[6] += p.x * w1; acc[7] += p.y * w1;
            p = __half22float2(*reinterpret_cast<__half2*>(&v2.x)); acc[0] += p.x * w2; acc[1] += p.y * w2;
            p = __half22float2(*reinterpret_cast<__half2*>(&v2.y)); acc[2] += p.x * w2; acc[3] += p.y * w2;
            p = __half22float2(*reinterpret_cast<__half2*>(&v2.z)); acc[4] += p.x * w2; acc[5] += p.y * w2;
            p = __half22float2(*reinterpret_cast<__half2*>(&v2.w)); acc[6] += p.x * w2; acc[7] += p.y * w2;
            p = __half22float2(*reinterpret_cast<__half2*>(&v3.x)); acc[0] += p.x * w3; acc[1] += p.y * w3;
            p = __half22float2(*reinterpret_cast<__half2*>(&v3.y)); acc[2] += p.x * w3; acc[3] += p.y * w3;
            p = __half22float2(*reinterpret_cast<__half2*>(&v3.z)); acc[4] += p.x * w3; acc[5] += p.y * w3;
            p = __half22float2(*reinterpret_cast<__half2*>(&v3.w)); acc[6] += p.x * w3; acc[7] += p.y * w3;
        }
    }
    for (; j < r1; j++) {
        int s = __ldg(&g_csrc[j]);
        float e = __ldg(&as1[s * 4 + h]) + adv;
        e = (e > 0.f) ? e : 0.2f * e;
        float w = __expf(e);
        uint4 hv = hm4[(size_t)s * 32 + lane];
        float2 p;
        p = __half22float2(*reinterpret_cast<__half2*>(&hv.x)); acc[0] += p.x * w; acc[1] += p.y * w;
        p = __half22float2(*reinterpret_cast<__half2*>(&hv.y)); acc[2] += p.x * w; acc[3] += p.y * w;
        p = __half22float2(*reinterpret_cast<__half2*>(&hv.z)); acc[4] += p.x * w; acc[5] += p.y * w;
        p = __half22float2(*reinterpret_cast<__half2*>(&hv.w)); acc[6] += p.x * w; acc[7] += p.y * w;
        dsum += w;
    }
    // combine partial halves via smem: odd warp publishes, even warp finalizes
    if (half == 1) {
        #pragma unroll
        for (int i = 0; i < 8; i++) sAcc[sub][lane * 8 + i] = acc[i];
        sDen[sub][lane] = dsum;
    }
    __syncthreads();
    if (half == 0 && active) {
        #pragma unroll
        for (int i = 0; i < 8; i++) acc[i] += sAcc[sub][lane * 8 + i];
        dsum += sDen[sub][lane];
        float inv = 1.f / (dsum + 1e-16f);
        size_t ob = (size_t)node * 256 + lane * 8;
        float4 b0 = *reinterpret_cast<const float4*>(&bias[lane * 8]);
        float4 b1 = *reinterpret_cast<const float4*>(&bias[lane * 8 + 4]);
        float o[8];
        o[0] = acc[0] * inv + b0.x; o[1] = acc[1] * inv + b0.y;
        o[2] = acc[2] * inv + b0.z; o[3] = acc[3] * inv + b0.w;
        o[4] = acc[4] * inv + b1.x; o[5] = acc[5] * inv + b1.y;
        o[6] = acc[6] * inv + b1.z; o[7] = acc[7] * inv + b1.w;
        #pragma unroll
        for (int i = 0; i < 8; i++) o[i] = (o[i] > 0.f) ? o[i] : (__expf(o[i]) - 1.f);
        *reinterpret_cast<float4*>(&out[ob])     = make_float4(o[0], o[1], o[2], o[3]);
        *reinterpret_cast<float4*>(&out[ob + 4]) = make_float4(o[4], o[5], o[6], o[7]);
    }
}

// ---------------- fused softmax + aggregation, layer 2 ----------------------
// TWO warps per node (half edge list each), smem combine. 4 nodes per block.
__global__ void agg2_kernel(const float* __restrict__ as2, const float* __restrict__ ad2,
                            const __half* __restrict__ hm, const float* __restrict__ bias,
                            float* __restrict__ out, int n) {
    __shared__ float sAcc[4][64];
    __shared__ float sDen[4][32];
    int tid = threadIdx.x;
    int warp = tid >> 5, lane = tid & 31;
    int sub = warp >> 1;
    int half = warp & 1;
    int node = blockIdx.x * 4 + sub;
    bool active = (node < n);
    int r0 = 0, r1 = 0;
    float adv = 0.f;
    if (active) {
        int a = g_rowptr[node], b = g_rowptr[node + 1];
        int mid = a + ((b - a) >> 1);
        r0 = half ? mid : a;
        r1 = half ? b : mid;
        adv = ad2[node];
    }
    const __half2* hm2 = reinterpret_cast<const __half2*>(hm);
    float2 acc = make_float2(0.f, 0.f);
    float dsum = 0.f;
    int j = r0;
    for (; j + 4 <= r1; j += 4) {
        int s0 = __ldg(&g_csrc[j]);
        int s1 = __ldg(&g_csrc[j + 1]);
        int s2 = __ldg(&g_csrc[j + 2]);
        int s3 = __ldg(&g_csrc[j + 3]);
        float e0 = __ldg(&as2[s0]);
        float e1 = __ldg(&as2[s1]);
        float e2 = __ldg(&as2[s2]);
        float e3 = __ldg(&as2[s3]);
        float2 v0 = __half22float2(hm2[(size_t)s0 * 32 + lane]);
        float2 v1 = __half22float2(hm2[(size_t)s1 * 32 + lane]);
        float2 v2 = __half22float2(hm2[(size_t)s2 * 32 + lane]);
        float2 v3 = __half22float2(hm2[(size_t)s3 * 32 + lane]);
        e0 += adv; e0 = (e0 > 0.f) ? e0 : 0.2f * e0; float w0 = __expf(e0);
        e1 += adv; e1 = (e1 > 0.f) ? e1 : 0.2f * e1; float w1 = __expf(e1);
        e2 += adv; e2 = (e2 > 0.f) ? e2 : 0.2f * e2; float w2 = __expf(e2);
        e3 += adv; e3 = (e3 > 0.f) ? e3 : 0.2f * e3; float w3 = __expf(e3);
        acc.x += v0.x * w0 + v1.x * w1 + v2.x * w2 + v3.x * w3;
        acc.y += v0.y * w0 + v1.y * w1 + v2.y * w2 + v3.y * w3;
        dsum += w0 + w1 + w2 + w3;
    }
    for (; j < r1; j++) {
        int s = __ldg(&g_csrc[j]);
        float e = __ldg(&as2[s]) + adv;
        e = (e > 0.f) ? e : 0.2f * e;
        float w = __expf(e);
        float2 hv = __half22float2(hm2[(size_t)s * 32 + lane]);
        acc.x += hv.x * w; acc.y += hv.y * w;
        dsum += w;
    }
    if (half == 1) {
        sAcc[sub][lane * 2]     = acc.x;
        sAcc[sub][lane * 2 + 1] = acc.y;
        sDen[sub][lane] = dsum;
    }
    __syncthreads();
    if (half == 0 && active) {
        acc.x += sAcc[sub][lane * 2];
        acc.y += sAcc[sub][lane * 2 + 1];
        dsum += sDen[sub][lane];
        float inv = 1.f / (dsum + 1e-16f);
        float2 bv = *reinterpret_cast<const float2*>(&bias[lane * 2]);
        *reinterpret_cast<float2*>(&out[(size_t)node * 64 + lane * 2]) =
            make_float2(acc.x * inv + bv.x, acc.y * inv + bv.y);
    }
}

// ---------------- launch ----------------------------------------------------
extern "C" void kernel_launch(void* const* d_in, const int* in_sizes, int n_in,
                              void* d_out, int out_size) {
    const float* x   = (const float*)d_in[0];
    const int*   ei  = (const int*)d_in[1];
    const float* W1  = (const float*)d_in[2];
    const float* a1s = (const float*)d_in[3];
    const float* a1d = (const float*)d_in[4];
    const float* b1  = (const float*)d_in[5];
    const float* W2  = (const float*)d_in[6];
    const float* a2s = (const float*)d_in[7];
    const float* a2d = (const float*)d_in[8];
    const float* b2  = (const float*)d_in[9];
    float* out = (float*)d_out;

    int N = in_sizes[0] / 128;
    int E = in_sizes[1] / 2;
    int EPN = E + N;
    int NB = (N + 1023) / 1024;
    int EQN = (E >> 2) + N;

    float *out1, *as1, *ad1, *as2, *ad2;
    __half *h1, *h2;
    cudaGetSymbolAddress((void**)&h1,   g_h1);
    cudaGetSymbolAddress((void**)&out1, g_out1);
    cudaGetSymbolAddress((void**)&h2,   g_h2);
    cudaGetSymbolAddress((void**)&as1,  g_as1);
    cudaGetSymbolAddress((void**)&ad1,  g_ad1);
    cudaGetSymbolAddress((void**)&as2,  g_as2);
    cudaGetSymbolAddress((void**)&ad2,  g_ad2);

    cudaStream_t s2 = g_res.s2;

    // fork: CSR build on s2, GEMM1 on the main (capture) stream
    cudaEventRecord(g_res.evFork, 0);
    cudaStreamWaitEvent(s2, g_res.evFork, 0);

    hist_kernel<<<(EQN + 255) / 256, 256, 0, s2>>>(ei, E, N);
    scan_local_kernel<<<NB, 1024, 0, s2>>>(N);
    scan_add_kernel<<<(N + 255) / 256, 256, 0, s2>>>(N, EPN, NB);
    scatter_kernel<<<(EQN + 255) / 256, 256, 0, s2>>>(ei, E, N);
    cudaEventRecord(g_res.evJoin, s2);

    gemm_tc_kernel<128, false><<<dim3(2, (N + 127) / 128), 256>>>(
        x, W1, h1, N, 128, 256, a1s, a1d, as1, ad1);

    // join: agg1 needs both the CSR and GEMM1 outputs
    cudaStreamWaitEvent(0, g_res.evJoin, 0);

    agg1_kernel<<<(N + 3) / 4, 256>>>(as1, ad1, h1, b1, out1, N);

    gemm_tc_kernel<64, true><<<dim3(1, (N + 127) / 128), 256>>>(
        out1, W2, h2, N, 256, 64, a2s, a2d, as2, ad2);
    agg2_kernel<<<(N + 3) / 4, 256>>>(as2, ad2, h2, b2, out, N);
}